// round 10
// baseline (speedup 1.0000x reference)
#include <cuda_runtime.h>
#include <math.h>

#define BB 4
#define SS 512
#define HH 768
#define DD 24
#define MM 96
#define RR (BB*SS)      // 2048
#define KX (3*HH)       // 2304
#define ZST 514         // padded transpose stride

typedef unsigned long long ull;

// ---------------- f32x2 packed helpers (pairwise kernel) ----------------
__device__ __forceinline__ ull pk2(float lo, float hi) {
    ull r; asm("mov.b64 %0, {%1, %2};" : "=l"(r) : "f"(lo), "f"(hi)); return r;
}
__device__ __forceinline__ ull dup2(float x) { return pk2(x, x); }
__device__ __forceinline__ void upk2(ull v, float& lo, float& hi) {
    asm("mov.b64 {%0, %1}, %2;" : "=f"(lo), "=f"(hi) : "l"(v));
}
__device__ __forceinline__ ull fma2(ull a, ull b, ull c) {
    ull d; asm("fma.rn.f32x2 %0, %1, %2, %3;" : "=l"(d) : "l"(a), "l"(b), "l"(c)); return d;
}
__device__ __forceinline__ ull abs2(ull a) { return a & 0x7fffffff7fffffffULL; }

// ---------------- tf32 helpers ----------------
__device__ __forceinline__ unsigned cvt_tf32(float x) {
    unsigned r; asm("cvt.rna.tf32.f32 %0, %1;" : "=r"(r) : "f"(x)); return r;
}
__device__ __forceinline__ void mma1688(float* c, const unsigned* a, const unsigned* b) {
    asm("mma.sync.aligned.m16n8k8.row.col.f32.tf32.tf32.f32 "
        "{%0,%1,%2,%3}, {%4,%5,%6,%7}, {%8,%9}, {%0,%1,%2,%3};"
        : "+f"(c[0]), "+f"(c[1]), "+f"(c[2]), "+f"(c[3])
        : "r"(a[0]), "r"(a[1]), "r"(a[2]), "r"(a[3]), "r"(b[0]), "r"(b[1]));
}

// ---------------- scratch ----------------
__device__ __align__(16) float g_Zj[BB*SS*DD];
__device__ __align__(16) float g_Zi[BB*SS*DD];
__device__ __align__(16) float g_probs[BB*SS*SS];
__device__ __align__(16) float g_ctx[BB*SS*HH];
__device__ __align__(16) float g_mhid[RR*HH];

// ---------------- K1: Z projections ----------------
__global__ void proj_kernel(const float* __restrict__ Hj, const float* __restrict__ Hi,
                            const float* __restrict__ Wpj, const float* __restrict__ Wpi)
{
    int which = blockIdx.y;
    const float* Hsrc = which ? Hi : Hj;
    const float* W    = which ? Wpi : Wpj;
    float* Z          = which ? g_Zi : g_Zj;
    int row = blockIdx.x * 8 + threadIdx.y;
    int col = threadIdx.x;
    const float* h = Hsrc + (size_t)row * HH;
    float acc = 0.f;
    #pragma unroll 8
    for (int k = 0; k < HH; ++k)
        acc = fmaf(h[k], W[k*DD + col], acc);
    Z[row*DD + col] = acc;
}

// ---------------- K2: fused pairwise scores + softmax -> probs (f32x2, fp32-exact) ----------------
// grid (SS, BB), block 256. Each warp: 16 q (8 packed pairs) per iteration, 4 iterations.
__global__ void __launch_bounds__(256) pairwise_kernel(
        const float* __restrict__ Ws1, const float* __restrict__ bs1,
        const float* __restrict__ ws2, const float* __restrict__ bs2p,
        const int*   __restrict__ mask)
{
    extern __shared__ float smem[];
    float2* sPair  = (float2*)smem;                   // DD*MM float2
    float*  sZiT   = smem + 2*DD*MM;                  // DD*ZST transposed [d][q]
    float*  sLog   = sZiT + DD*ZST;                   // SS
    float*  sBias  = sLog + SS;                       // MM
    float*  sZj    = sBias + MM;                      // DD
    float*  sRed   = sZj + DD;                        // 32

    int b = blockIdx.y, p = blockIdx.x;
    int tid = threadIdx.x;
    int lane = tid & 31, warp = tid >> 5;

    if (tid < DD) sZj[tid] = g_Zj[((size_t)b*SS + p)*DD + tid];
    __syncthreads();

    {
        const float4* src = (const float4*)(g_Zi + (size_t)b*SS*DD);
        for (int i = tid; i < SS*DD/4; i += 256) {
            float4 v = src[i];
            int q = (4*i) / DD, d0 = (4*i) % DD;   // DD%4==0 -> never crosses a row
            sZiT[(d0+0)*ZST+q] = v.x;
            sZiT[(d0+1)*ZST+q] = v.y;
            sZiT[(d0+2)*ZST+q] = v.z;
            sZiT[(d0+3)*ZST+q] = v.w;
        }
    }
    for (int idx = tid; idx < DD*MM; idx += 256) {
        int d = idx / MM, m = idx - d*MM;
        float w1i = Ws1[(DD   + d)*MM + m];
        float w1h = Ws1[(2*DD + d)*MM + m];
        float w1d = Ws1[(3*DD + d)*MM + m];
        sPair[idx] = make_float2(fmaf(sZj[d], w1h, w1i), w1d);
    }
    if (tid < MM) {
        float acc = bs1[tid];
        #pragma unroll
        for (int d = 0; d < DD; ++d)
            acc = fmaf(sZj[d], Ws1[d*MM + tid], acc);
        sBias[tid] = acc;
    }
    __syncthreads();

    float zj[DD];
    #pragma unroll
    for (int d = 0; d < DD; ++d) zj[d] = sZj[d];

    int m0 = lane, m1 = lane + 32, m2 = lane + 64;
    float wsa = ws2[m0], wsb = ws2[m1], wsc = ws2[m2];
    ull bi0p = dup2(sBias[m0]), bi1p = dup2(sBias[m1]), bi2p = dup2(sBias[m2]);
    const ull NEG1 = dup2(-1.0f);
    float bsc = bs2p[0];
    const int* mrow = mask + b*SS;

    // each warp handles 16 q per iteration (8 packed pairs); 8 warps * 16 q * 4 iters = 512
    for (int it = 0; it < 4; ++it) {
        int qb = it*128 + warp*16;
        ull acc0[8], acc1[8], acc2[8];
        #pragma unroll
        for (int j = 0; j < 8; ++j) { acc0[j]=bi0p; acc1[j]=bi1p; acc2[j]=bi2p; }

        #pragma unroll
        for (int d = 0; d < DD; ++d) {
            const ull* zr = (const ull*)&sZiT[d*ZST + qb];   // 8B-aligned broadcast LDS.64
            ull zp[8];
            #pragma unroll
            for (int j = 0; j < 8; ++j) zp[j] = zr[j];
            ull zjd = dup2(zj[d]);
            ull fp[8];
            #pragma unroll
            for (int j = 0; j < 8; ++j) fp[j] = abs2(fma2(zp[j], NEG1, zjd));
            float2 w0 = sPair[d*MM + m0];
            float2 w1 = sPair[d*MM + m1];
            float2 w2 = sPair[d*MM + m2];
            ull wc0 = dup2(w0.x), wd0 = dup2(w0.y);
            ull wc1 = dup2(w1.x), wd1 = dup2(w1.y);
            ull wc2 = dup2(w2.x), wd2 = dup2(w2.y);
            #pragma unroll
            for (int j = 0; j < 8; ++j) {
                acc0[j] = fma2(zp[j], wc0, acc0[j]); acc0[j] = fma2(fp[j], wd0, acc0[j]);
                acc1[j] = fma2(zp[j], wc1, acc1[j]); acc1[j] = fma2(fp[j], wd1, acc1[j]);
                acc2[j] = fma2(zp[j], wc2, acc2[j]); acc2[j] = fma2(fp[j], wd2, acc2[j]);
            }
        }

        #pragma unroll
        for (int j = 0; j < 8; ++j) {
            float l0,h0,l1,h1,l2,h2;
            upk2(acc0[j], l0, h0); upk2(acc1[j], l1, h1); upk2(acc2[j], l2, h2);
            float sl = fmaxf(l0,0.f)*wsa + fmaxf(l1,0.f)*wsb + fmaxf(l2,0.f)*wsc;
            float sh = fmaxf(h0,0.f)*wsa + fmaxf(h1,0.f)*wsb + fmaxf(h2,0.f)*wsc;
            #pragma unroll
            for (int o = 16; o; o >>= 1) {
                sl += __shfl_xor_sync(0xffffffffu, sl, o);
                sh += __shfl_xor_sync(0xffffffffu, sh, o);
            }
            if (lane == 0) {
                int q0 = qb + 2*j;
                float lg0 = sl + bsc, lg1 = sh + bsc;
                if (mrow[q0]   == 0) lg0 = -3.0e38f;
                if (mrow[q0+1] == 0) lg1 = -3.0e38f;
                sLog[q0]   = lg0;
                sLog[q0+1] = lg1;
            }
        }
    }
    __syncthreads();

    // block softmax over 512 logits
    float v = -3.4e38f;
    for (int i = tid; i < SS; i += 256) v = fmaxf(v, sLog[i]);
    #pragma unroll
    for (int o = 16; o; o >>= 1) v = fmaxf(v, __shfl_xor_sync(0xffffffffu, v, o));
    if (lane == 0) sRed[warp] = v;
    __syncthreads();
    float gmax = sRed[0];
    #pragma unroll
    for (int w = 1; w < 8; ++w) gmax = fmaxf(gmax, sRed[w]);
    __syncthreads();

    float ls = 0.f;
    for (int i = tid; i < SS; i += 256) {
        float e = expf(sLog[i] - gmax);
        sLog[i] = e;
        ls += e;
    }
    #pragma unroll
    for (int o = 16; o; o >>= 1) ls += __shfl_xor_sync(0xffffffffu, ls, o);
    if (lane == 0) sRed[warp] = ls;
    __syncthreads();
    float gsum = 0.f;
    #pragma unroll
    for (int w = 0; w < 8; ++w) gsum += sRed[w];
    float inv = 1.f / gsum;

    float* prow = g_probs + ((size_t)b*SS + p)*SS;
    for (int i = tid; i < SS; i += 256) prow[i] = sLog[i] * inv;
}

// ---------------- tf32 tensor-core GEMM, 64x64 tile, 256 threads, BK=32, in-block split-K ----------------
// (unchanged — proven 527us config)
template<int MODE, bool FUSE>
__global__ void __launch_bounds__(256) gemm_tf32(
        const float* __restrict__ A, const float* __restrict__ Bm, float* __restrict__ C,
        int K, int N, size_t strA, size_t strB, size_t strC,
        const float* __restrict__ bias, const float* __restrict__ alphap,
        const float* __restrict__ Ctx, const float* __restrict__ HjP)
{
    A  += (size_t)blockIdx.z * strA;
    Bm += (size_t)blockIdx.z * strB;
    C  += (size_t)blockIdx.z * strC;

    __shared__ __align__(16) unsigned shMem[8192];
    unsigned (*shA)[2048] = (unsigned(*)[2048])shMem;
    unsigned (*shB)[2048] = (unsigned(*)[2048])(shMem + 4096);
    float* sRedu = (float*)shMem;

    int tid = threadIdx.x;
    int lane = tid & 31, warp = tid >> 5;
    int wg = warp >> 2, wsub = warp & 3;
    int warp_m = wsub >> 1, warp_n = wsub & 1;
    int blockM = blockIdx.y * 64, blockN = blockIdx.x * 64;

    float acc[2][4][4];
    #pragma unroll
    for (int mi = 0; mi < 2; ++mi)
        #pragma unroll
        for (int ni = 0; ni < 4; ++ni)
            #pragma unroll
            for (int r = 0; r < 4; ++r) acc[mi][ni][r] = 0.f;

    int lm = lane >> 2, lk = lane & 3;

    auto stageA = [&](int kt, float ra[2][4]) {
        #pragma unroll
        for (int i = 0; i < 2; ++i) {
            int at = warp*2 + i;
            int ks = at >> 2, mt = at & 3;
            int m  = blockM + mt*16 + lm;
            int kg = kt + ks*8 + lk;
            if (FUSE) {
                int region = (kg >= 2*HH) ? 2 : ((kg >= HH) ? 1 : 0);
                int kh = kg - region*HH;
                size_t o00 = (size_t)m*HH + kh;
                size_t o10 = o00 + (size_t)8*HH;
                if (region == 0) {
                    ra[i][0] = Ctx[o00];     ra[i][1] = Ctx[o10];
                    ra[i][2] = Ctx[o00 + 4]; ra[i][3] = Ctx[o10 + 4];
                } else if (region == 1) {
                    ra[i][0] = HjP[o00];     ra[i][1] = HjP[o10];
                    ra[i][2] = HjP[o00 + 4]; ra[i][3] = HjP[o10 + 4];
                } else {
                    ra[i][0] = Ctx[o00]     * HjP[o00];
                    ra[i][1] = Ctx[o10]     * HjP[o10];
                    ra[i][2] = Ctx[o00 + 4] * HjP[o00 + 4];
                    ra[i][3] = Ctx[o10 + 4] * HjP[o10 + 4];
                }
            } else {
                const float* p0 = A + (size_t)m*K + kg;
                ra[i][0] = p0[0];
                ra[i][1] = p0[(size_t)8*K];
                ra[i][2] = p0[4];
                ra[i][3] = p0[(size_t)8*K + 4];
            }
        }
    };
    auto commitA = [&](const float ra[2][4], unsigned* dst) {
        #pragma unroll
        for (int i = 0; i < 2; ++i) {
            int at = warp*2 + i;
            uint4 v;
            v.x = cvt_tf32(ra[i][0]); v.y = cvt_tf32(ra[i][1]);
            v.z = cvt_tf32(ra[i][2]); v.w = cvt_tf32(ra[i][3]);
            *(uint4*)&dst[at*128 + lane*4] = v;
        }
    };
    auto stageB = [&](int kt, float rb[4][2]) {
        #pragma unroll
        for (int i = 0; i < 4; ++i) {
            int tb = warp*4 + i;
            int ks = tb >> 3, nt = tb & 7;
            int kg = kt + ks*8 + lk;
            int n  = blockN + nt*8 + lm;
            const float* p0 = Bm + (size_t)kg*N + n;
            rb[i][0] = p0[0];
            rb[i][1] = p0[(size_t)4*N];
        }
    };
    auto commitB = [&](const float rb[4][2], unsigned* dst) {
        #pragma unroll
        for (int i = 0; i < 4; ++i) {
            int tb = warp*4 + i;
            uint2 v;
            v.x = cvt_tf32(rb[i][0]); v.y = cvt_tf32(rb[i][1]);
            *(uint2*)&dst[tb*64 + lane*2] = v;
        }
    };

    {
        float ra[2][4], rb[4][2];
        stageA(0, ra); stageB(0, rb);
        commitA(ra, shA[0]); commitB(rb, shB[0]);
    }
    __syncthreads();

    int buf = 0;
    for (int kt = 0; kt < K; kt += 32) {
        float ra[2][4], rb[4][2];
        bool more = (kt + 32) < K;
        if (more) { stageA(kt + 32, ra); stageB(kt + 32, rb); }

        #pragma unroll
        for (int ksl = 0; ksl < 2; ++ksl) {
            int ks = wg*2 + ksl;
            unsigned afr[2][4], bfr[4][2];
            #pragma unroll
            for (int mi = 0; mi < 2; ++mi)
                *(uint4*)afr[mi] = *(const uint4*)&shA[buf][(ks*4 + warp_m*2 + mi)*128 + lane*4];
            #pragma unroll
            for (int ni = 0; ni < 4; ++ni)
                *(uint2*)bfr[ni] = *(const uint2*)&shB[buf][(ks*8 + warp_n*4 + ni)*64 + lane*2];
            #pragma unroll
            for (int mi = 0; mi < 2; ++mi)
                #pragma unroll
                for (int ni = 0; ni < 4; ++ni)
                    mma1688(acc[mi][ni], afr[mi], bfr[ni]);
        }

        if (more) { commitA(ra, shA[buf^1]); commitB(rb, shB[buf^1]); }
        __syncthreads();
        buf ^= 1;
    }

    if (wg == 1) {
        #pragma unroll
        for (int mi = 0; mi < 2; ++mi)
            #pragma unroll
            for (int ni = 0; ni < 4; ++ni) {
                int t = (wsub*2 + mi)*4 + ni;
                *(float4*)&sRedu[t*128 + lane*4] = *(const float4*)acc[mi][ni];
            }
    }
    __syncthreads();
    if (wg == 0) {
        float al = (MODE == 2) ? *alphap : 1.f;
        #pragma unroll
        for (int mi = 0; mi < 2; ++mi) {
            int r0 = blockM + warp_m*32 + mi*16 + lm;
            #pragma unroll
            for (int ni = 0; ni < 4; ++ni) {
                int t = (wsub*2 + mi)*4 + ni;
                float4 part = *(const float4*)&sRedu[t*128 + lane*4];
                int c0 = blockN + warp_n*32 + ni*8 + lk*2;
                float b0 = 0.f, b1 = 0.f;
                if (MODE != 0) { float2 bv = *(const float2*)(bias + c0); b0 = bv.x; b1 = bv.y; }
                float v0 = acc[mi][ni][0] + part.x + b0;
                float v1 = acc[mi][ni][1] + part.y + b1;
                float v2 = acc[mi][ni][2] + part.z + b0;
                float v3 = acc[mi][ni][3] + part.w + b1;
                if (MODE == 1) {
                    v0 = fmaxf(v0, 0.f); v1 = fmaxf(v1, 0.f);
                    v2 = fmaxf(v2, 0.f); v3 = fmaxf(v3, 0.f);
                }
                if (MODE == 2) { v0 *= al; v1 *= al; v2 *= al; v3 *= al; }
                float2 lo; lo.x = v0; lo.y = v1;
                float2 hi; hi.x = v2; hi.y = v3;
                *(float2*)&C[(size_t)r0*N + c0]       = lo;
                *(float2*)&C[(size_t)(r0 + 8)*N + c0] = hi;
            }
        }
    }
}

// ---------------- launch ----------------
extern "C" void kernel_launch(void* const* d_in, const int* in_sizes, int n_in,
                              void* d_out, int out_size)
{
    const float* Hj   = (const float*)d_in[0];
    const float* Hi   = (const float*)d_in[1];
    const float* Wpj  = (const float*)d_in[2];
    const float* Wpi  = (const float*)d_in[3];
    const float* Ws1  = (const float*)d_in[4];
    const float* bs1  = (const float*)d_in[5];
    const float* ws2  = (const float*)d_in[6];
    const float* bs2  = (const float*)d_in[7];
    const float* Wv1  = (const float*)d_in[8];
    const float* bv1  = (const float*)d_in[9];
    const float* Wv2  = (const float*)d_in[10];
    const float* bv2  = (const float*)d_in[11];
    const float* alph = (const float*)d_in[12];
    const int*   amask= (const int*)d_in[13];
    float* out = (float*)d_out;

    float *pProbs, *pCtx, *pMhid;
    cudaGetSymbolAddress((void**)&pProbs, g_probs);
    cudaGetSymbolAddress((void**)&pCtx,   g_ctx);
    cudaGetSymbolAddress((void**)&pMhid,  g_mhid);

    // K1: projections
    proj_kernel<<<dim3(RR/8, 2), dim3(24, 8)>>>(Hj, Hi, Wpj, Wpi);

    // K2: pairwise + softmax (fp32-exact)
    const size_t smemPW = (size_t)(2*DD*MM + DD*ZST + SS + MM + DD + 32) * sizeof(float);
    cudaFuncSetAttribute(pairwise_kernel, cudaFuncAttributeMaxDynamicSharedMemorySize, (int)smemPW);
    pairwise_kernel<<<dim3(SS, BB), 256, smemPW>>>(Ws1, bs1, ws2, bs2, amask);

    // K3: ctx = probs @ H_i   (per batch: M=512, K=512, N=768)
    gemm_tf32<0, false><<<dim3(HH/64, SS/64, BB), 256>>>(
        pProbs, Hi, pCtx, SS, HH,
        (size_t)SS*SS, (size_t)SS*HH, (size_t)SS*HH, nullptr, nullptr, nullptr, nullptr);

    // K4: mhid = relu(X @ Wv1 + bv1), X = [ctx|Hj|ctx*Hj] on the fly (M=2048, K=2304, N=768)
    gemm_tf32<1, true><<<dim3(HH/64, RR/64, 1), 256>>>(
        nullptr, Wv1, pMhid, KX, HH, 0, 0, 0, bv1, nullptr, pCtx, Hj);

    // K5: out = alpha * (mhid @ Wv2 + bv2)  (M=2048, K=768, N=768)
    gemm_tf32<2, false><<<dim3(HH/64, RR/64, 1), 256>>>(
        pMhid, Wv2, out, HH, HH, 0, 0, 0, bv2, alph, nullptr, nullptr);
}

// round 11
// speedup vs baseline: 1.3932x; 1.3932x over previous
#include <cuda_runtime.h>
#include <math.h>

#define BB 4
#define SS 512
#define HH 768
#define DD 24
#define MM 96
#define RR (BB*SS)      // 2048
#define KX (3*HH)       // 2304
#define ZST 514         // padded transpose stride

typedef unsigned long long ull;

// ---------------- tf32 helpers ----------------
__device__ __forceinline__ unsigned cvt_tf32(float x) {
    unsigned r; asm("cvt.rna.tf32.f32 %0, %1;" : "=r"(r) : "f"(x)); return r;
}
__device__ __forceinline__ void mma1688(float* c, const unsigned* a, const unsigned* b) {
    asm("mma.sync.aligned.m16n8k8.row.col.f32.tf32.tf32.f32 "
        "{%0,%1,%2,%3}, {%4,%5,%6,%7}, {%8,%9}, {%0,%1,%2,%3};"
        : "+f"(c[0]), "+f"(c[1]), "+f"(c[2]), "+f"(c[3])
        : "r"(a[0]), "r"(a[1]), "r"(a[2]), "r"(a[3]), "r"(b[0]), "r"(b[1]));
}

// ---------------- scratch ----------------
__device__ __align__(16) float g_Zj[BB*SS*DD];
__device__ __align__(16) float g_Zi[BB*SS*DD];
__device__ __align__(16) float g_probs[BB*SS*SS];
__device__ __align__(16) float g_ctx[BB*SS*HH];
__device__ __align__(16) float g_mhid[RR*HH];

// ---------------- K1: Z projections ----------------
__global__ void proj_kernel(const float* __restrict__ Hj, const float* __restrict__ Hi,
                            const float* __restrict__ Wpj, const float* __restrict__ Wpi)
{
    int which = blockIdx.y;
    const float* Hsrc = which ? Hi : Hj;
    const float* W    = which ? Wpi : Wpj;
    float* Z          = which ? g_Zi : g_Zj;
    int row = blockIdx.x * 8 + threadIdx.y;
    int col = threadIdx.x;
    const float* h = Hsrc + (size_t)row * HH;
    float acc = 0.f;
    #pragma unroll 8
    for (int k = 0; k < HH; ++k)
        acc = fmaf(h[k], W[k*DD + col], acc);
    Z[row*DD + col] = acc;
}

// ---------------- K2: pairwise scores via tf32 tensor cores + softmax ----------------
// Per block (b, p): act(512x96) = [Zi | |Zj_p - Zi|](512x48) @ [Wcomb_p; W1d](48x96) + bias_p
// logits[q] = relu(act) . ws2 + bs2 -> softmax -> probs row.
// 8 warps: warp_m = warp>>1 (8 mtiles of 16 q each), warp_n = warp&1 (48-col half).
// A frags built on the fly from sZiT; B frags (72 tiles) built once into smem.
__global__ void __launch_bounds__(256) pairwise_kernel(
        const float* __restrict__ Ws1, const float* __restrict__ bs1,
        const float* __restrict__ ws2, const float* __restrict__ bs2p,
        const int*   __restrict__ mask)
{
    extern __shared__ float smem[];
    float*    sZiT  = smem;                       // DD*ZST (12336) transposed [d][q]
    unsigned* sBf   = (unsigned*)(smem + DD*ZST); // 72 frag-tiles * 64 words = 4608
    float*    sL2   = smem + DD*ZST + 4608;       // 2 x 512 partial logits
    float*    sBias = sL2 + 2*SS;                 // 96
    float*    sWs2  = sBias + MM;                 // 96
    float*    sZj   = sWs2 + MM;                  // 24
    float*    sRed  = sZj + DD;                   // 32

    int b = blockIdx.y, p = blockIdx.x;
    int tid = threadIdx.x;
    int lane = tid & 31, warp = tid >> 5;
    int lm = lane >> 2, lk = lane & 3;
    int warp_m = warp >> 1, warp_n = warp & 1;

    if (tid < DD) sZj[tid] = g_Zj[((size_t)b*SS + p)*DD + tid];
    if (tid >= 128 && tid < 128 + MM) sWs2[tid - 128] = ws2[tid - 128];
    __syncthreads();

    // transpose Zi[b] into sZiT[d][q]
    {
        const float4* src = (const float4*)(g_Zi + (size_t)b*SS*DD);
        for (int i = tid; i < SS*DD/4; i += 256) {
            float4 v = src[i];
            int q = (4*i) / DD, d0 = (4*i) % DD;   // DD%4==0 -> never crosses a row
            sZiT[(d0+0)*ZST+q] = v.x;
            sZiT[(d0+1)*ZST+q] = v.y;
            sZiT[(d0+2)*ZST+q] = v.z;
            sZiT[(d0+3)*ZST+q] = v.w;
        }
    }
    // B fragment tiles: ft = kt*12 + nt; element (k, n): k<DD -> Wcomb = W1i + Zj*W1h; else W1d
    // W1d row for k>=DD: Ws1[(3*DD + k - DD)] = Ws1[(2*DD + k)]
    {
        int ft0 = warp * 9;
        #pragma unroll
        for (int i = 0; i < 9; ++i) {
            int ft = ft0 + i;
            int kt = ft / 12, nt = ft - kt*12;
            int n  = nt*8 + lm;
            unsigned v[2];
            #pragma unroll
            for (int j = 0; j < 2; ++j) {
                int k = kt*8 + lk + j*4;
                float w;
                if (k < DD)
                    w = fmaf(sZj[k], Ws1[(2*DD + k)*MM + n], Ws1[(DD + k)*MM + n]);
                else
                    w = Ws1[(2*DD + k)*MM + n];
                v[j] = cvt_tf32(w);
            }
            *(uint2*)&sBf[ft*64 + lane*2] = make_uint2(v[0], v[1]);
        }
    }
    // bias_p[m] = tj[p][m] + bs1[m]
    if (tid < MM) {
        float acc = bs1[tid];
        #pragma unroll
        for (int d = 0; d < DD; ++d)
            acc = fmaf(sZj[d], Ws1[d*MM + tid], acc);
        sBias[tid] = acc;
    }
    __syncthreads();

    // per-thread preloads
    float zjk[3][2];
    #pragma unroll
    for (int t = 0; t < 3; ++t) {
        zjk[t][0] = sZj[t*8 + lk];
        zjk[t][1] = sZj[t*8 + lk + 4];
    }
    float bb[6][2], ww[6][2];
    #pragma unroll
    for (int nt = 0; nt < 6; ++nt) {
        int c = warp_n*48 + nt*8 + lk*2;
        bb[nt][0] = sBias[c];  bb[nt][1] = sBias[c+1];
        ww[nt][0] = sWs2[c];   ww[nt][1] = sWs2[c+1];
    }

    // mainloop: 8 mtiles per warp, K=48 (6 ktiles), N=48 (6 ntiles)
    for (int mt = 0; mt < 8; ++mt) {
        int row = (warp_m*8 + mt)*16 + lm;     // rows row, row+8
        float acc[6][4];
        #pragma unroll
        for (int nt = 0; nt < 6; ++nt)
            #pragma unroll
            for (int r = 0; r < 4; ++r) acc[nt][r] = 0.f;

        #pragma unroll
        for (int kt = 0; kt < 6; ++kt) {
            unsigned a[4];
            if (kt < 3) {
                int kd = kt*8 + lk;
                a[0] = cvt_tf32(sZiT[kd*ZST + row]);
                a[1] = cvt_tf32(sZiT[kd*ZST + row + 8]);
                a[2] = cvt_tf32(sZiT[(kd+4)*ZST + row]);
                a[3] = cvt_tf32(sZiT[(kd+4)*ZST + row + 8]);
            } else {
                int kd = (kt-3)*8 + lk;
                float z0 = zjk[kt-3][0], z1 = zjk[kt-3][1];
                a[0] = cvt_tf32(fabsf(z0 - sZiT[kd*ZST + row]));
                a[1] = cvt_tf32(fabsf(z0 - sZiT[kd*ZST + row + 8]));
                a[2] = cvt_tf32(fabsf(z1 - sZiT[(kd+4)*ZST + row]));
                a[3] = cvt_tf32(fabsf(z1 - sZiT[(kd+4)*ZST + row + 8]));
            }
            #pragma unroll
            for (int nt = 0; nt < 6; ++nt) {
                uint2 bf = *(const uint2*)&sBf[(kt*12 + warp_n*6 + nt)*64 + lane*2];
                unsigned bfr[2] = {bf.x, bf.y};
                mma1688(acc[nt], a, bfr);
            }
        }

        // epilogue: relu(act + bias) . ws2 over this warp's 48 cols
        float s0 = 0.f, s8 = 0.f;
        #pragma unroll
        for (int nt = 0; nt < 6; ++nt) {
            s0 += fmaxf(acc[nt][0] + bb[nt][0], 0.f) * ww[nt][0]
                + fmaxf(acc[nt][1] + bb[nt][1], 0.f) * ww[nt][1];
            s8 += fmaxf(acc[nt][2] + bb[nt][0], 0.f) * ww[nt][0]
                + fmaxf(acc[nt][3] + bb[nt][1], 0.f) * ww[nt][1];
        }
        s0 += __shfl_xor_sync(0xffffffffu, s0, 1);
        s0 += __shfl_xor_sync(0xffffffffu, s0, 2);
        s8 += __shfl_xor_sync(0xffffffffu, s8, 1);
        s8 += __shfl_xor_sync(0xffffffffu, s8, 2);
        if (lk == 0) {
            sL2[warp_n*SS + row]     = s0;
            sL2[warp_n*SS + row + 8] = s8;
        }
    }
    __syncthreads();

    // combine halves + bias + mask -> logits in sL2[0]
    float bsc = bs2p[0];
    const int* mrow = mask + b*SS;
    for (int i = tid; i < SS; i += 256) {
        float lg = sL2[i] + sL2[SS + i] + bsc;
        if (mrow[i] == 0) lg = -3.0e38f;
        sL2[i] = lg;
    }
    __syncthreads();

    // block softmax over 512 logits
    float v = -3.4e38f;
    for (int i = tid; i < SS; i += 256) v = fmaxf(v, sL2[i]);
    #pragma unroll
    for (int o = 16; o; o >>= 1) v = fmaxf(v, __shfl_xor_sync(0xffffffffu, v, o));
    if (lane == 0) sRed[warp] = v;
    __syncthreads();
    float gmax = sRed[0];
    #pragma unroll
    for (int w = 1; w < 8; ++w) gmax = fmaxf(gmax, sRed[w]);
    __syncthreads();

    float ls = 0.f;
    for (int i = tid; i < SS; i += 256) {
        float e = expf(sL2[i] - gmax);
        sL2[i] = e;
        ls += e;
    }
    #pragma unroll
    for (int o = 16; o; o >>= 1) ls += __shfl_xor_sync(0xffffffffu, ls, o);
    if (lane == 0) sRed[warp] = ls;
    __syncthreads();
    float gsum = 0.f;
    #pragma unroll
    for (int w = 0; w < 8; ++w) gsum += sRed[w];
    float inv = 1.f / gsum;

    float* prow = g_probs + ((size_t)b*SS + p)*SS;
    for (int i = tid; i < SS; i += 256) prow[i] = sL2[i] * inv;
}

// ---------------- tf32 tensor-core GEMM, 64x64 tile, 256 threads, BK=32, in-block split-K ----------------
// (unchanged -- proven 527us config)
template<int MODE, bool FUSE>
__global__ void __launch_bounds__(256) gemm_tf32(
        const float* __restrict__ A, const float* __restrict__ Bm, float* __restrict__ C,
        int K, int N, size_t strA, size_t strB, size_t strC,
        const float* __restrict__ bias, const float* __restrict__ alphap,
        const float* __restrict__ Ctx, const float* __restrict__ HjP)
{
    A  += (size_t)blockIdx.z * strA;
    Bm += (size_t)blockIdx.z * strB;
    C  += (size_t)blockIdx.z * strC;

    __shared__ __align__(16) unsigned shMem[8192];
    unsigned (*shA)[2048] = (unsigned(*)[2048])shMem;
    unsigned (*shB)[2048] = (unsigned(*)[2048])(shMem + 4096);
    float* sRedu = (float*)shMem;

    int tid = threadIdx.x;
    int lane = tid & 31, warp = tid >> 5;
    int wg = warp >> 2, wsub = warp & 3;
    int warp_m = wsub >> 1, warp_n = wsub & 1;
    int blockM = blockIdx.y * 64, blockN = blockIdx.x * 64;

    float acc[2][4][4];
    #pragma unroll
    for (int mi = 0; mi < 2; ++mi)
        #pragma unroll
        for (int ni = 0; ni < 4; ++ni)
            #pragma unroll
            for (int r = 0; r < 4; ++r) acc[mi][ni][r] = 0.f;

    int lm = lane >> 2, lk = lane & 3;

    auto stageA = [&](int kt, float ra[2][4]) {
        #pragma unroll
        for (int i = 0; i < 2; ++i) {
            int at = warp*2 + i;
            int ks = at >> 2, mt = at & 3;
            int m  = blockM + mt*16 + lm;
            int kg = kt + ks*8 + lk;
            if (FUSE) {
                int region = (kg >= 2*HH) ? 2 : ((kg >= HH) ? 1 : 0);
                int kh = kg - region*HH;
                size_t o00 = (size_t)m*HH + kh;
                size_t o10 = o00 + (size_t)8*HH;
                if (region == 0) {
                    ra[i][0] = Ctx[o00];     ra[i][1] = Ctx[o10];
                    ra[i][2] = Ctx[o00 + 4]; ra[i][3] = Ctx[o10 + 4];
                } else if (region == 1) {
                    ra[i][0] = HjP[o00];     ra[i][1] = HjP[o10];
                    ra[i][2] = HjP[o00 + 4]; ra[i][3] = HjP[o10 + 4];
                } else {
                    ra[i][0] = Ctx[o00]     * HjP[o00];
                    ra[i][1] = Ctx[o10]     * HjP[o10];
                    ra[i][2] = Ctx[o00 + 4] * HjP[o00 + 4];
                    ra[i][3] = Ctx[o10 + 4] * HjP[o10 + 4];
                }
            } else {
                const float* p0 = A + (size_t)m*K + kg;
                ra[i][0] = p0[0];
                ra[i][1] = p0[(size_t)8*K];
                ra[i][2] = p0[4];
                ra[i][3] = p0[(size_t)8*K + 4];
            }
        }
    };
    auto commitA = [&](const float ra[2][4], unsigned* dst) {
        #pragma unroll
        for (int i = 0; i < 2; ++i) {
            int at = warp*2 + i;
            uint4 v;
            v.x = cvt_tf32(ra[i][0]); v.y = cvt_tf32(ra[i][1]);
            v.z = cvt_tf32(ra[i][2]); v.w = cvt_tf32(ra[i][3]);
            *(uint4*)&dst[at*128 + lane*4] = v;
        }
    };
    auto stageB = [&](int kt, float rb[4][2]) {
        #pragma unroll
        for (int i = 0; i < 4; ++i) {
            int tb = warp*4 + i;
            int ks = tb >> 3, nt = tb & 7;
            int kg = kt + ks*8 + lk;
            int n  = blockN + nt*8 + lm;
            const float* p0 = Bm + (size_t)kg*N + n;
            rb[i][0] = p0[0];
            rb[i][1] = p0[(size_t)4*N];
        }
    };
    auto commitB = [&](const float rb[4][2], unsigned* dst) {
        #pragma unroll
        for (int i = 0; i < 4; ++i) {
            int tb = warp*4 + i;
            uint2 v;
            v.x = cvt_tf32(rb[i][0]); v.y = cvt_tf32(rb[i][1]);
            *(uint2*)&dst[tb*64 + lane*2] = v;
        }
    };

    {
        float ra[2][4], rb[4][2];
        stageA(0, ra); stageB(0, rb);
        commitA(ra, shA[0]); commitB(rb, shB[0]);
    }
    __syncthreads();

    int buf = 0;
    for (int kt = 0; kt < K; kt += 32) {
        float ra[2][4], rb[4][2];
        bool more = (kt + 32) < K;
        if (more) { stageA(kt + 32, ra); stageB(kt + 32, rb); }

        #pragma unroll
        for (int ksl = 0; ksl < 2; ++ksl) {
            int ks = wg*2 + ksl;
            unsigned afr[2][4], bfr[4][2];
            #pragma unroll
            for (int mi = 0; mi < 2; ++mi)
                *(uint4*)afr[mi] = *(const uint4*)&shA[buf][(ks*4 + warp_m*2 + mi)*128 + lane*4];
            #pragma unroll
            for (int ni = 0; ni < 4; ++ni)
                *(uint2*)bfr[ni] = *(const uint2*)&shB[buf][(ks*8 + warp_n*4 + ni)*64 + lane*2];
            #pragma unroll
            for (int mi = 0; mi < 2; ++mi)
                #pragma unroll
                for (int ni = 0; ni < 4; ++ni)
                    mma1688(acc[mi][ni], afr[mi], bfr[ni]);
        }

        if (more) { commitA(ra, shA[buf^1]); commitB(rb, shB[buf^1]); }
        __syncthreads();
        buf ^= 1;
    }

    if (wg == 1) {
        #pragma unroll
        for (int mi = 0; mi < 2; ++mi)
            #pragma unroll
            for (int ni = 0; ni < 4; ++ni) {
                int t = (wsub*2 + mi)*4 + ni;
                *(float4*)&sRedu[t*128 + lane*4] = *(const float4*)acc[mi][ni];
            }
    }
    __syncthreads();
    if (wg == 0) {
        float al = (MODE == 2) ? *alphap : 1.f;
        #pragma unroll
        for (int mi = 0; mi < 2; ++mi) {
            int r0 = blockM + warp_m*32 + mi*16 + lm;
            #pragma unroll
            for (int ni = 0; ni < 4; ++ni) {
                int t = (wsub*2 + mi)*4 + ni;
                float4 part = *(const float4*)&sRedu[t*128 + lane*4];
                int c0 = blockN + warp_n*32 + ni*8 + lk*2;
                float b0 = 0.f, b1 = 0.f;
                if (MODE != 0) { float2 bv = *(const float2*)(bias + c0); b0 = bv.x; b1 = bv.y; }
                float v0 = acc[mi][ni][0] + part.x + b0;
                float v1 = acc[mi][ni][1] + part.y + b1;
                float v2 = acc[mi][ni][2] + part.z + b0;
                float v3 = acc[mi][ni][3] + part.w + b1;
                if (MODE == 1) {
                    v0 = fmaxf(v0, 0.f); v1 = fmaxf(v1, 0.f);
                    v2 = fmaxf(v2, 0.f); v3 = fmaxf(v3, 0.f);
                }
                if (MODE == 2) { v0 *= al; v1 *= al; v2 *= al; v3 *= al; }
                float2 lo; lo.x = v0; lo.y = v1;
                float2 hi; hi.x = v2; hi.y = v3;
                *(float2*)&C[(size_t)r0*N + c0]       = lo;
                *(float2*)&C[(size_t)(r0 + 8)*N + c0] = hi;
            }
        }
    }
}

// ---------------- launch ----------------
extern "C" void kernel_launch(void* const* d_in, const int* in_sizes, int n_in,
                              void* d_out, int out_size)
{
    const float* Hj   = (const float*)d_in[0];
    const float* Hi   = (const float*)d_in[1];
    const float* Wpj  = (const float*)d_in[2];
    const float* Wpi  = (const float*)d_in[3];
    const float* Ws1  = (const float*)d_in[4];
    const float* bs1  = (const float*)d_in[5];
    const float* ws2  = (const float*)d_in[6];
    const float* bs2  = (const float*)d_in[7];
    const float* Wv1  = (const float*)d_in[8];
    const float* bv1  = (const float*)d_in[9];
    const float* Wv2  = (const float*)d_in[10];
    const float* bv2  = (const float*)d_in[11];
    const float* alph = (const float*)d_in[12];
    const int*   amask= (const int*)d_in[13];
    float* out = (float*)d_out;

    float *pProbs, *pCtx, *pMhid;
    cudaGetSymbolAddress((void**)&pProbs, g_probs);
    cudaGetSymbolAddress((void**)&pCtx,   g_ctx);
    cudaGetSymbolAddress((void**)&pMhid,  g_mhid);

    // K1: projections
    proj_kernel<<<dim3(RR/8, 2), dim3(24, 8)>>>(Hj, Hi, Wpj, Wpi);

    // K2: pairwise scores on tensor cores + softmax
    const size_t smemPW = (size_t)(DD*ZST + 4608 + 2*SS + MM + MM + DD + 32) * sizeof(float);
    cudaFuncSetAttribute(pairwise_kernel, cudaFuncAttributeMaxDynamicSharedMemorySize, (int)smemPW);
    pairwise_kernel<<<dim3(SS, BB), 256, smemPW>>>(Ws1, bs1, ws2, bs2, amask);

    // K3: ctx = probs @ H_i   (per batch: M=512, K=512, N=768)
    gemm_tf32<0, false><<<dim3(HH/64, SS/64, BB), 256>>>(
        pProbs, Hi, pCtx, SS, HH,
        (size_t)SS*SS, (size_t)SS*HH, (size_t)SS*HH, nullptr, nullptr, nullptr, nullptr);

    // K4: mhid = relu(X @ Wv1 + bv1), X = [ctx|Hj|ctx*Hj] on the fly (M=2048, K=2304, N=768)
    gemm_tf32<1, true><<<dim3(HH/64, RR/64, 1), 256>>>(
        nullptr, Wv1, pMhid, KX, HH, 0, 0, 0, bv1, nullptr, pCtx, Hj);

    // K5: out = alpha * (mhid @ Wv2 + bv2)  (M=2048, K=768, N=768)
    gemm_tf32<2, false><<<dim3(HH/64, RR/64, 1), 256>>>(
        pMhid, Wv2, out, HH, HH, 0, 0, 0, bv2, alph, nullptr, nullptr);
}